// round 6
// baseline (speedup 1.0000x reference)
#include <cuda_runtime.h>

// dW[i,j] = sum_{a,b,c} coeffs[a,b,c] * x[j]^a * y[i]^b * w[i,j]^c
// N_POST = N_PRE = 8192, fp32. Streaming kernel at the HBM roofline.
//
// r[a][c] = sum_b coeffs[a,b,c]*y[i]^b  (9 per-row floats, smem table)
// s_c     = r[0][c] + x*r[1][c] + x^2*r[2][c]
// dW      = s0 + w*(s1 + w*s2)
//
// Block = 4 rows x 2048 cols. x float4s loaded ONCE per thread and reused
// across 4 rows (x L2 traffic /4, 6 fewer in-loop LDG per thread).
// w read streaming (__ldcs), out stored streaming (__stcs).

#define N_PRE  8192
#define N_POST 8192
#define THREADS 256
#define ROWS 4                       // rows per block
#define BCOLS 2048                   // columns per block
#define F4T (BCOLS / 4 / THREADS)    // float4 per thread per row = 2
#define COL_BLOCKS (N_PRE / BCOLS)   // 4

__global__ __launch_bounds__(THREADS)
void taylor3_kernel(const float* __restrict__ x,
                    const float* __restrict__ y,
                    const float4* __restrict__ w4,
                    const float* __restrict__ coeffs,
                    float4* __restrict__ out4)
{
    __shared__ float rtab[ROWS][9];

    const int colBlock = blockIdx.x & (COL_BLOCKS - 1);
    const int r0       = (blockIdx.x >> 2) * ROWS;
    const int tid      = threadIdx.x;

    // Cooperative per-row coefficient table: 36 threads, one (row, a, c) each.
    if (tid < ROWS * 9) {
        const int rr  = tid / 9;
        const int idx = tid - rr * 9;
        const int a   = idx / 3;
        const int c   = idx - a * 3;
        const float yi = __ldg(&y[r0 + rr]);
        const float y2 = yi * yi;
        const float c0 = __ldg(&coeffs[a * 9 + 0 + c]);
        const float c1 = __ldg(&coeffs[a * 9 + 3 + c]);
        const float c2 = __ldg(&coeffs[a * 9 + 6 + c]);
        rtab[rr][idx] = fmaf(y2, c2, fmaf(yi, c1, c0));
    }

    // x loaded once, reused for all ROWS rows.
    const float4* __restrict__ x4 = (const float4*)x;
    const int cb = colBlock * (BCOLS / 4);        // float4 col base
    float4 xv[F4T];
#pragma unroll
    for (int k = 0; k < F4T; ++k)
        xv[k] = __ldg(&x4[cb + k * THREADS + tid]);

    __syncthreads();

#pragma unroll
    for (int rr = 0; rr < ROWS; ++rr) {
        float r[9];
#pragma unroll
        for (int i = 0; i < 9; ++i) r[i] = rtab[rr][i];   // broadcast LDS

        const long base = (long)(r0 + rr) * (N_PRE / 4);

#pragma unroll
        for (int k = 0; k < F4T; ++k) {
            const int c4 = cb + k * THREADS + tid;
            const float4 wv = __ldcs(&w4[base + c4]);

            float4 ov;
#pragma unroll
            for (int e = 0; e < 4; ++e) {
                const float xj = (&xv[k].x)[e];
                const float wj = (&wv.x)[e];
                const float x2 = xj * xj;
                const float s0 = fmaf(x2, r[6], fmaf(xj, r[3], r[0]));
                const float s1 = fmaf(x2, r[7], fmaf(xj, r[4], r[1]));
                const float s2 = fmaf(x2, r[8], fmaf(xj, r[5], r[2]));
                (&ov.x)[e] = fmaf(wj, fmaf(wj, s2, s1), s0);
            }

            __stcs(&out4[base + c4], ov);
        }
    }
}

extern "C" void kernel_launch(void* const* d_in, const int* in_sizes, int n_in,
                              void* d_out, int out_size)
{
    const float* x      = (const float*)d_in[0];   // [8192]
    const float* y      = (const float*)d_in[1];   // [8192]
    const float* w      = (const float*)d_in[2];   // [8192, 8192]
    const float* coeffs = (const float*)d_in[3];   // [3,3,3]
    float* out          = (float*)d_out;           // [8192, 8192]

    const int blocks = COL_BLOCKS * (N_POST / ROWS);   // 8192
    taylor3_kernel<<<blocks, THREADS>>>(x, y, (const float4*)w, coeffs,
                                        (float4*)out);
}

// round 7
// speedup vs baseline: 1.1641x; 1.1641x over previous
#include <cuda_runtime.h>

// dW[i,j] = sum_{a,b,c} coeffs[a,b,c] * x[j]^a * y[i]^b * w[i,j]^c
// N_POST = N_PRE = 8192, fp32. Streaming kernel at the HBM roofline.
//
// r[a][c] = sum_b coeffs[a,b,c]*y[i]^b  (9 per-row floats)
// s_c     = r[0][c] + x*r[1][c] + x^2*r[2][c]
// dW      = s0 + w*(s1 + w*s2)
//
// One block per row: 256 threads x 8 float4 = 8192 columns, processed as
// 2 batches of 4. Each batch front-issues 4 independent LDG.128 pairs
// (2KB contiguous read burst per warp), then 4 compute+STG.128 (2KB write
// burst). __launch_bounds__(256,5) raises the reg budget to 51 so ptxas
// can keep the batch resident instead of sinking the loads (R4 failure).
// Cache policy (proven R3): w streamed (__ldcs), out streamed (__stcs),
// x cached (__ldg).

#define N_PRE  8192
#define N_POST 8192
#define THREADS 256
#define BATCH 4
#define NBATCH 2                 // BATCH * NBATCH * THREADS * 4 = 8192 cols

__global__ __launch_bounds__(THREADS, 5)
void taylor3_kernel(const float* __restrict__ x,
                    const float* __restrict__ y,
                    const float4* __restrict__ w4,
                    const float* __restrict__ coeffs,
                    float4* __restrict__ out4)
{
    const int row = blockIdx.x;

    const float yi = __ldg(&y[row]);
    const float y2 = yi * yi;

    // r[a][c] = coeffs[a,0,c] + yi*coeffs[a,1,c] + y2*coeffs[a,2,c]
    float r[3][3];
#pragma unroll
    for (int a = 0; a < 3; ++a) {
#pragma unroll
        for (int c = 0; c < 3; ++c) {
            const float c0 = __ldg(&coeffs[a * 9 + 0 + c]);
            const float c1 = __ldg(&coeffs[a * 9 + 3 + c]);
            const float c2 = __ldg(&coeffs[a * 9 + 6 + c]);
            r[a][c] = fmaf(y2, c2, fmaf(yi, c1, c0));
        }
    }

    const long rowBase = (long)row * (N_PRE / 4);
    const float4* __restrict__ x4 = (const float4*)x;

#pragma unroll
    for (int b = 0; b < NBATCH; ++b) {
        const int cbase = b * BATCH * THREADS + threadIdx.x;

        // Front-batched independent loads: 4 LDG.128 w + 4 LDG.128 x,
        // no consumer between them.
        float4 wv[BATCH], xv[BATCH];
#pragma unroll
        for (int k = 0; k < BATCH; ++k) {
            const int c4 = cbase + k * THREADS;
            wv[k] = __ldcs(&w4[rowBase + c4]);
            xv[k] = __ldg(&x4[c4]);
        }

        // Compute + batched stores.
#pragma unroll
        for (int k = 0; k < BATCH; ++k) {
            const int c4 = cbase + k * THREADS;
            float4 ov;
#pragma unroll
            for (int e = 0; e < 4; ++e) {
                const float xj = (&xv[k].x)[e];
                const float wj = (&wv[k].x)[e];
                const float x2 = xj * xj;
                const float s0 = fmaf(x2, r[2][0], fmaf(xj, r[1][0], r[0][0]));
                const float s1 = fmaf(x2, r[2][1], fmaf(xj, r[1][1], r[0][1]));
                const float s2 = fmaf(x2, r[2][2], fmaf(xj, r[1][2], r[0][2]));
                (&ov.x)[e] = fmaf(wj, fmaf(wj, s2, s1), s0);
            }
            __stcs(&out4[rowBase + c4], ov);
        }
    }
}

extern "C" void kernel_launch(void* const* d_in, const int* in_sizes, int n_in,
                              void* d_out, int out_size)
{
    const float* x      = (const float*)d_in[0];   // [8192]
    const float* y      = (const float*)d_in[1];   // [8192]
    const float* w      = (const float*)d_in[2];   // [8192, 8192]
    const float* coeffs = (const float*)d_in[3];   // [3,3,3]
    float* out          = (float*)d_out;           // [8192, 8192]

    taylor3_kernel<<<N_POST, THREADS>>>(x, y, (const float4*)w, coeffs,
                                        (float4*)out);
}